// round 1
// baseline (speedup 1.0000x reference)
#include <cuda_runtime.h>
#include <cuda_bf16.h>
#include <cstdint>

// GAT 2-layer fused implementation.
// Reference math per layer:
//   Wh = h @ W                      [N,D]
//   s  = Wh @ a_src ; d = Wh @ a_dst   [N]
//   e[i,j] = leaky_relu(s_i + d_j, 0.2), masked by adj
//   attn = softmax_row(e) ; out = relu(attn @ Wh)
//
// Attention logits are rank-1 (+mask), so P is generated on the fly inside the
// P @ Wh GEMM. Stabilizer: m_i = lrelu(s_i + max_j d_j) >= e[i,j] (lrelu monotone).

#define N_NODES 8192
#define DIM 256

__device__ float g_Wh[N_NODES * DIM];
__device__ float g_h1[N_NODES * DIM];
__device__ float g_s[N_NODES];
__device__ float g_d[N_NODES];
__device__ float g_maxd;

__device__ __forceinline__ float lrelu(float x) { return x > 0.f ? x : 0.2f * x; }

// ---------------------------------------------------------------------------
// GEMM: C[N,D] = A[N,D] @ B[D,D]   (Wh = h @ W)
// BM=64, BN=64, BK=16; 256 threads (16x16), 4x4 micro-tile.
// grid = (D/64, N/64)
// ---------------------------------------------------------------------------
__global__ void __launch_bounds__(256) gemm_wh(const float* __restrict__ A,
                                               const float* __restrict__ B,
                                               float* __restrict__ C) {
    __shared__ float As[64 * 16];
    __shared__ float Bs[16 * 64];
    const int t = threadIdx.x;
    const int tx = t & 15;          // 0..15 (cols)
    const int ty = t >> 4;          // 0..15 (rows)
    const int i0 = blockIdx.y * 64;
    const int c0 = blockIdx.x * 64;

    float acc[4][4] = {};

    for (int k0 = 0; k0 < DIM; k0 += 16) {
        __syncthreads();
        {
            int e = t * 4;
            int r = e >> 4, kk = e & 15;
            float4 av = *(const float4*)&A[(size_t)(i0 + r) * DIM + k0 + kk];
            *(float4*)&As[e] = av;
        }
        {
            int e = t * 4;
            int kr = e >> 6, cc = e & 63;
            float4 bv = *(const float4*)&B[(size_t)(k0 + kr) * DIM + c0 + cc];
            *(float4*)&Bs[e] = bv;
        }
        __syncthreads();

        #pragma unroll
        for (int k = 0; k < 16; k++) {
            float a[4];
            #pragma unroll
            for (int m = 0; m < 4; m++) a[m] = As[(ty * 4 + m) * 16 + k];
            float4 bb = *(float4*)&Bs[k * 64 + tx * 4];
            float b[4] = {bb.x, bb.y, bb.z, bb.w};
            #pragma unroll
            for (int m = 0; m < 4; m++)
                #pragma unroll
                for (int n = 0; n < 4; n++)
                    acc[m][n] = fmaf(a[m], b[n], acc[m][n]);
        }
    }

    #pragma unroll
    for (int m = 0; m < 4; m++) {
        #pragma unroll
        for (int n = 0; n < 4; n++) {
            C[(size_t)(i0 + ty * 4 + m) * DIM + c0 + tx * 4 + n] = acc[m][n];
        }
    }
}

// ---------------------------------------------------------------------------
// s_i = Wh[i,:] . a_src ; d_i = Wh[i,:] . a_dst    (one warp per row)
// ---------------------------------------------------------------------------
__global__ void __launch_bounds__(256) compute_sd(const float* __restrict__ Wh,
                                                  const float* __restrict__ a_src,
                                                  const float* __restrict__ a_dst) {
    int warp = (blockIdx.x * blockDim.x + threadIdx.x) >> 5;
    int lane = threadIdx.x & 31;
    if (warp >= N_NODES) return;
    const float* row = Wh + (size_t)warp * DIM;
    float ps = 0.f, pd = 0.f;
    #pragma unroll
    for (int c = lane; c < DIM; c += 32) {
        float v = row[c];
        ps = fmaf(v, a_src[c], ps);
        pd = fmaf(v, a_dst[c], pd);
    }
    #pragma unroll
    for (int o = 16; o > 0; o >>= 1) {
        ps += __shfl_down_sync(0xffffffffu, ps, o);
        pd += __shfl_down_sync(0xffffffffu, pd, o);
    }
    if (lane == 0) {
        g_s[warp] = ps;
        g_d[warp] = pd;
    }
}

// ---------------------------------------------------------------------------
// Global max of d (single block)
// ---------------------------------------------------------------------------
__global__ void __launch_bounds__(1024) reduce_maxd() {
    __shared__ float sm[1024];
    int t = threadIdx.x;
    float m = -3.0e38f;
    for (int i = t; i < N_NODES; i += 1024) m = fmaxf(m, g_d[i]);
    sm[t] = m;
    __syncthreads();
    for (int o = 512; o > 0; o >>= 1) {
        if (t < o) sm[t] = fmaxf(sm[t], sm[t + o]);
        __syncthreads();
    }
    if (t == 0) g_maxd = sm[0];
}

// ---------------------------------------------------------------------------
// Fused attention * Wh:
//   out[i,:] = relu( (1/Z_i) * sum_j p_ij * Wh[j,:] )
//   p_ij = adj[i,j] ? exp(lrelu(s_i + d_j) - m_i) : 0 ; m_i = lrelu(s_i + maxd)
// BM=64 rows, full 256 cols per block, BK=16 over j.
// 256 threads: ty=t/32 (8 row groups x 8 rows), tx=t%32 (32 col groups x 8 cols)
// grid = N/64 = 128 blocks
// ---------------------------------------------------------------------------
__global__ void __launch_bounds__(256, 1) gat_main(const float* __restrict__ Wh,
                                                   const int* __restrict__ adj,
                                                   float* __restrict__ out) {
    __shared__ float sp[64 * 17];       // padded p tile [64][16] (stride 17)
    __shared__ float sv[16 * 256];      // V tile
    __shared__ float sz[64];            // row sums Z

    const int t = threadIdx.x;
    const int ty = t >> 5;              // 0..7
    const int tx = t & 31;              // 0..31
    const int i0 = blockIdx.x * 64;

    // p-generation assignment: thread t covers row pr = t/4, cols kb..kb+3
    const int pr = t >> 2;
    const int kb = (t & 3) * 4;
    const float s_r = g_s[i0 + pr];
    const float m_r = lrelu(s_r + g_maxd);

    float acc[8][8] = {};
    float zacc = 0.f;

    const size_t adj_row = (size_t)(i0 + pr) * N_NODES;

    for (int j0 = 0; j0 < N_NODES; j0 += 16) {
        __syncthreads();   // previous iteration's consumers done

        // --- build p tile ---
        {
            int4 aj = *(const int4*)&adj[adj_row + j0 + kb];
            float4 dd = *(const float4*)&g_d[j0 + kb];
            float p0 = aj.x ? __expf(lrelu(s_r + dd.x) - m_r) : 0.f;
            float p1 = aj.y ? __expf(lrelu(s_r + dd.y) - m_r) : 0.f;
            float p2 = aj.z ? __expf(lrelu(s_r + dd.z) - m_r) : 0.f;
            float p3 = aj.w ? __expf(lrelu(s_r + dd.w) - m_r) : 0.f;
            sp[pr * 17 + kb + 0] = p0;
            sp[pr * 17 + kb + 1] = p1;
            sp[pr * 17 + kb + 2] = p2;
            sp[pr * 17 + kb + 3] = p3;
        }
        // --- load V tile (16 consecutive Wh rows = 4096 contiguous floats) ---
        {
            const float4* src = (const float4*)(Wh + (size_t)j0 * DIM);
            float4* dst = (float4*)sv;
            #pragma unroll
            for (int w = 0; w < 4; w++) dst[t + 256 * w] = src[t + 256 * w];
        }
        __syncthreads();

        // --- Z accumulation (threads 0..63, row t) ---
        if (t < 64) {
            float zz = 0.f;
            #pragma unroll
            for (int k = 0; k < 16; k++) zz += sp[t * 17 + k];
            zacc += zz;
        }

        // --- GEMM micro-tile ---
        #pragma unroll
        for (int k = 0; k < 16; k++) {
            float pv[8];
            #pragma unroll
            for (int m = 0; m < 8; m++) pv[m] = sp[(ty * 8 + m) * 17 + k];
            float4 v0 = *(float4*)&sv[k * 256 + tx * 8];
            float4 v1 = *(float4*)&sv[k * 256 + tx * 8 + 4];
            #pragma unroll
            for (int m = 0; m < 8; m++) {
                acc[m][0] = fmaf(pv[m], v0.x, acc[m][0]);
                acc[m][1] = fmaf(pv[m], v0.y, acc[m][1]);
                acc[m][2] = fmaf(pv[m], v0.z, acc[m][2]);
                acc[m][3] = fmaf(pv[m], v0.w, acc[m][3]);
                acc[m][4] = fmaf(pv[m], v1.x, acc[m][4]);
                acc[m][5] = fmaf(pv[m], v1.y, acc[m][5]);
                acc[m][6] = fmaf(pv[m], v1.z, acc[m][6]);
                acc[m][7] = fmaf(pv[m], v1.w, acc[m][7]);
            }
        }
    }

    if (t < 64) sz[t] = zacc;
    __syncthreads();

    #pragma unroll
    for (int m = 0; m < 8; m++) {
        float z = sz[ty * 8 + m];
        float rz = (z > 0.f) ? (1.0f / z) : 0.f;
        #pragma unroll
        for (int n = 0; n < 8; n++) {
            float v = acc[m][n] * rz;
            out[(size_t)(i0 + ty * 8 + m) * DIM + tx * 8 + n] = fmaxf(v, 0.f);
        }
    }
}

// ---------------------------------------------------------------------------
static void run_layer(const float* h_in, const int* adj, const float* W,
                      const float* a_src, const float* a_dst, float* out) {
    float* Wh;
    cudaGetSymbolAddress((void**)&Wh, g_Wh);

    dim3 ggrid(DIM / 64, N_NODES / 64);
    gemm_wh<<<ggrid, 256>>>(h_in, W, Wh);
    compute_sd<<<(N_NODES * 32) / 256, 256>>>(Wh, a_src, a_dst);
    reduce_maxd<<<1, 1024>>>();
    gat_main<<<N_NODES / 64, 256>>>(Wh, adj, out);
}

extern "C" void kernel_launch(void* const* d_in, const int* in_sizes, int n_in,
                              void* d_out, int out_size) {
    const float* x      = (const float*)d_in[0];
    const int*   adj    = (const int*)d_in[1];
    const float* W1     = (const float*)d_in[2];
    const float* a1_src = (const float*)d_in[3];
    const float* a1_dst = (const float*)d_in[4];
    const float* W2     = (const float*)d_in[5];
    const float* a2_src = (const float*)d_in[6];
    const float* a2_dst = (const float*)d_in[7];
    float* out = (float*)d_out;

    float* h1;
    cudaGetSymbolAddress((void**)&h1, g_h1);

    run_layer(x, adj, W1, a1_src, a1_dst, h1);
    run_layer(h1, adj, W2, a2_src, a2_dst, out);
}

// round 2
// speedup vs baseline: 1.8280x; 1.8280x over previous
#include <cuda_runtime.h>
#include <cuda_bf16.h>
#include <cstdint>

// GAT 2-layer fused. Rank-1 logits: e[i,j] = lrelu(s_i + d_j), masked by adj.
// P generated on the fly inside a tf32 tensor-core P @ Wh GEMM.
// Stabilizer: m_i = lrelu(s_i + max_j d_j) (lrelu monotone).

#define N_NODES 8192
#define DIM 256

__device__ float g_Wh[N_NODES * DIM];
__device__ float g_h1[N_NODES * DIM];
__device__ float g_s[N_NODES];
__device__ float g_d[N_NODES];
__device__ float g_maxd;

__device__ __forceinline__ float lrelu(float x) { return x > 0.f ? x : 0.2f * x; }

__device__ __forceinline__ float tf32r(float x) {
    uint32_t u;
    asm("cvt.rna.tf32.f32 %0, %1;" : "=r"(u) : "f"(x));
    return __uint_as_float(u);
}

__device__ __forceinline__ void mma_tf32(float4& c, const uint32_t a[4],
                                         uint32_t b0, uint32_t b1) {
    asm volatile(
        "mma.sync.aligned.m16n8k8.row.col.f32.tf32.tf32.f32 "
        "{%0,%1,%2,%3}, {%4,%5,%6,%7}, {%8,%9}, {%0,%1,%2,%3};"
        : "+f"(c.x), "+f"(c.y), "+f"(c.z), "+f"(c.w)
        : "r"(a[0]), "r"(a[1]), "r"(a[2]), "r"(a[3]), "r"(b0), "r"(b1));
}

// ---------------------------------------------------------------------------
// GEMM: C[N,D] = A[N,D] @ B[D,D]   (Wh = h @ W), fp32 SIMT (small: ~1 GFLOP)
// ---------------------------------------------------------------------------
__global__ void __launch_bounds__(256) gemm_wh(const float* __restrict__ A,
                                               const float* __restrict__ B,
                                               float* __restrict__ C) {
    __shared__ float As[64 * 16];
    __shared__ float Bs[16 * 64];
    const int t = threadIdx.x;
    const int tx = t & 15;
    const int ty = t >> 4;
    const int i0 = blockIdx.y * 64;
    const int c0 = blockIdx.x * 64;

    float acc[4][4] = {};

    for (int k0 = 0; k0 < DIM; k0 += 16) {
        __syncthreads();
        {
            int e = t * 4;
            int r = e >> 4, kk = e & 15;
            float4 av = *(const float4*)&A[(size_t)(i0 + r) * DIM + k0 + kk];
            *(float4*)&As[e] = av;
        }
        {
            int e = t * 4;
            int kr = e >> 6, cc = e & 63;
            float4 bv = *(const float4*)&B[(size_t)(k0 + kr) * DIM + c0 + cc];
            *(float4*)&Bs[e] = bv;
        }
        __syncthreads();

        #pragma unroll
        for (int k = 0; k < 16; k++) {
            float a[4];
            #pragma unroll
            for (int m = 0; m < 4; m++) a[m] = As[(ty * 4 + m) * 16 + k];
            float4 bb = *(float4*)&Bs[k * 64 + tx * 4];
            float b[4] = {bb.x, bb.y, bb.z, bb.w};
            #pragma unroll
            for (int m = 0; m < 4; m++)
                #pragma unroll
                for (int n = 0; n < 4; n++)
                    acc[m][n] = fmaf(a[m], b[n], acc[m][n]);
        }
    }

    #pragma unroll
    for (int m = 0; m < 4; m++)
        #pragma unroll
        for (int n = 0; n < 4; n++)
            C[(size_t)(i0 + ty * 4 + m) * DIM + c0 + tx * 4 + n] = acc[m][n];
}

// ---------------------------------------------------------------------------
__global__ void __launch_bounds__(256) compute_sd(const float* __restrict__ Wh,
                                                  const float* __restrict__ a_src,
                                                  const float* __restrict__ a_dst) {
    int warp = (blockIdx.x * blockDim.x + threadIdx.x) >> 5;
    int lane = threadIdx.x & 31;
    if (warp >= N_NODES) return;
    const float* row = Wh + (size_t)warp * DIM;
    float ps = 0.f, pd = 0.f;
    #pragma unroll
    for (int c = lane; c < DIM; c += 32) {
        float v = row[c];
        ps = fmaf(v, a_src[c], ps);
        pd = fmaf(v, a_dst[c], pd);
    }
    #pragma unroll
    for (int o = 16; o > 0; o >>= 1) {
        ps += __shfl_down_sync(0xffffffffu, ps, o);
        pd += __shfl_down_sync(0xffffffffu, pd, o);
    }
    if (lane == 0) { g_s[warp] = ps; g_d[warp] = pd; }
}

__global__ void __launch_bounds__(1024) reduce_maxd() {
    __shared__ float sm[1024];
    int t = threadIdx.x;
    float m = -3.0e38f;
    for (int i = t; i < N_NODES; i += 1024) m = fmaxf(m, g_d[i]);
    sm[t] = m;
    __syncthreads();
    for (int o = 512; o > 0; o >>= 1) {
        if (t < o) sm[t] = fmaxf(sm[t], sm[t + o]);
        __syncthreads();
    }
    if (t == 0) g_maxd = sm[0];
}

// ---------------------------------------------------------------------------
// Fused attention * Wh on tf32 tensor cores.
// BM=64 rows, BN=256 (all cols), BK=16 over j, double-buffered smem.
// 256 threads = 8 warps: 2 (M) x 4 (N) warp grid; warp tile M32 x N64.
// mma m16n8k8: per warp per iter: 2 m-tiles x 8 n-tiles x 2 k-chunks = 32 MMA.
// grid = N/64 = 128 blocks.
// ---------------------------------------------------------------------------
#define PA_STRIDE 20   // 64 x 16 P tile, row stride 20 (conflict-free A frags)
#define SV_STRIDE 264  // 16 x 256 V tile, row stride 264 (conflict-free B frags)

__global__ void __launch_bounds__(256, 1) gat_main(const float* __restrict__ Wh,
                                                   const int* __restrict__ adj,
                                                   float* __restrict__ out) {
    __shared__ float spA[2][64 * PA_STRIDE];
    __shared__ float sv[2][16 * SV_STRIDE];
    __shared__ float sz[64];

    const int t = threadIdx.x;
    const int lane = t & 31;
    const int warp = t >> 5;
    const int warpM = warp >> 2;        // 0..1
    const int warpN = warp & 3;         // 0..3
    const int gid = lane >> 2;          // 0..7
    const int tig = lane & 3;           // 0..3
    const int i0 = blockIdx.x * 64;

    // P-generation assignment: thread t covers row pr, cols kb..kb+3
    const int pr = t >> 2;
    const int kb = (t & 3) * 4;
    const float s_r = g_s[i0 + pr];
    const float m_r = lrelu(s_r + g_maxd);
    const int* adjrow = adj + (size_t)(i0 + pr) * N_NODES;

    float4 acc[2][8];
    #pragma unroll
    for (int m = 0; m < 2; m++)
        #pragma unroll
        for (int n = 0; n < 8; n++) acc[m][n] = make_float4(0.f, 0.f, 0.f, 0.f);
    float zacc = 0.f;

    // ---- prefetch iter 0 ----
    int4 aj = *(const int4*)&adjrow[kb];
    float4 dd = *(const float4*)&g_d[kb];
    float4 vv[4];
    {
        const float4* vsrc = (const float4*)Wh;
        #pragma unroll
        for (int w = 0; w < 4; w++) vv[w] = vsrc[t + 256 * w];
    }

    // ---- write buffer 0 ----
    {
        float* pA = spA[0] + pr * PA_STRIDE + kb;
        pA[0] = tf32r(aj.x ? __expf(lrelu(s_r + dd.x) - m_r) : 0.f);
        pA[1] = tf32r(aj.y ? __expf(lrelu(s_r + dd.y) - m_r) : 0.f);
        pA[2] = tf32r(aj.z ? __expf(lrelu(s_r + dd.z) - m_r) : 0.f);
        pA[3] = tf32r(aj.w ? __expf(lrelu(s_r + dd.w) - m_r) : 0.f);
        #pragma unroll
        for (int w = 0; w < 4; w++) {
            int idx = t + 256 * w;
            int row = idx >> 6, c4 = (idx & 63) * 4;
            float* dst = sv[0] + row * SV_STRIDE + c4;
            dst[0] = tf32r(vv[w].x); dst[1] = tf32r(vv[w].y);
            dst[2] = tf32r(vv[w].z); dst[3] = tf32r(vv[w].w);
        }
    }
    __syncthreads();

    const int NIT = N_NODES / 16;   // 512
    for (int it = 0; it < NIT; ++it) {
        const int cur = it & 1, nxt = cur ^ 1;
        const int jn = (it + 1 < NIT) ? (it + 1) * 16 : 0;

        // ---- prefetch next tiles into registers ----
        aj = *(const int4*)&adjrow[jn + kb];
        dd = *(const float4*)&g_d[jn + kb];
        {
            const float4* vsrc = (const float4*)(Wh + (size_t)jn * DIM);
            #pragma unroll
            for (int w = 0; w < 4; w++) vv[w] = vsrc[t + 256 * w];
        }

        const float* A = spA[cur];
        const float* V = sv[cur];

        // ---- Z accumulation (threads 0..63, row t) ----
        if (t < 64) {
            float zz = 0.f;
            #pragma unroll
            for (int k = 0; k < 16; k++) zz += A[t * PA_STRIDE + k];
            zacc += zz;
        }

        // ---- tensor-core GEMM on current tiles ----
        #pragma unroll
        for (int kc = 0; kc < 2; kc++) {
            uint32_t a[2][4];
            #pragma unroll
            for (int mt = 0; mt < 2; mt++) {
                int r = warpM * 32 + mt * 16 + gid;
                int c = kc * 8 + tig;
                a[mt][0] = __float_as_uint(A[r * PA_STRIDE + c]);
                a[mt][1] = __float_as_uint(A[(r + 8) * PA_STRIDE + c]);
                a[mt][2] = __float_as_uint(A[r * PA_STRIDE + c + 4]);
                a[mt][3] = __float_as_uint(A[(r + 8) * PA_STRIDE + c + 4]);
            }
            #pragma unroll
            for (int nt = 0; nt < 8; nt++) {
                int n = warpN * 64 + nt * 8 + gid;
                int k = kc * 8 + tig;
                uint32_t b0 = __float_as_uint(V[k * SV_STRIDE + n]);
                uint32_t b1 = __float_as_uint(V[(k + 4) * SV_STRIDE + n]);
                mma_tf32(acc[0][nt], a[0], b0, b1);
                mma_tf32(acc[1][nt], a[1], b0, b1);
            }
        }

        // ---- write prefetched tiles to the other buffer ----
        {
            float* pA = spA[nxt] + pr * PA_STRIDE + kb;
            pA[0] = tf32r(aj.x ? __expf(lrelu(s_r + dd.x) - m_r) : 0.f);
            pA[1] = tf32r(aj.y ? __expf(lrelu(s_r + dd.y) - m_r) : 0.f);
            pA[2] = tf32r(aj.z ? __expf(lrelu(s_r + dd.z) - m_r) : 0.f);
            pA[3] = tf32r(aj.w ? __expf(lrelu(s_r + dd.w) - m_r) : 0.f);
            #pragma unroll
            for (int w = 0; w < 4; w++) {
                int idx = t + 256 * w;
                int row = idx >> 6, c4 = (idx & 63) * 4;
                float* dst = sv[nxt] + row * SV_STRIDE + c4;
                dst[0] = tf32r(vv[w].x); dst[1] = tf32r(vv[w].y);
                dst[2] = tf32r(vv[w].z); dst[3] = tf32r(vv[w].w);
            }
        }
        __syncthreads();
    }

    if (t < 64) sz[t] = zacc;
    __syncthreads();

    // ---- epilogue: divide by Z, relu, store ----
    #pragma unroll
    for (int mt = 0; mt < 2; mt++) {
        int rloc0 = warpM * 32 + mt * 16 + gid;
        int rloc1 = rloc0 + 8;
        float z0 = sz[rloc0], z1 = sz[rloc1];
        float rz0 = (z0 > 0.f) ? (1.f / z0) : 0.f;
        float rz1 = (z1 > 0.f) ? (1.f / z1) : 0.f;
        #pragma unroll
        for (int nt = 0; nt < 8; nt++) {
            int col = warpN * 64 + nt * 8 + 2 * tig;
            float4 c = acc[mt][nt];
            float2 o0 = make_float2(fmaxf(c.x * rz0, 0.f), fmaxf(c.y * rz0, 0.f));
            float2 o1 = make_float2(fmaxf(c.z * rz1, 0.f), fmaxf(c.w * rz1, 0.f));
            *(float2*)&out[(size_t)(i0 + rloc0) * DIM + col] = o0;
            *(float2*)&out[(size_t)(i0 + rloc1) * DIM + col] = o1;
        }
    }
}

// ---------------------------------------------------------------------------
static void run_layer(const float* h_in, const int* adj, const float* W,
                      const float* a_src, const float* a_dst, float* out) {
    float* Wh;
    cudaGetSymbolAddress((void**)&Wh, g_Wh);

    dim3 ggrid(DIM / 64, N_NODES / 64);
    gemm_wh<<<ggrid, 256>>>(h_in, W, Wh);
    compute_sd<<<(N_NODES * 32) / 256, 256>>>(Wh, a_src, a_dst);
    reduce_maxd<<<1, 1024>>>();
    gat_main<<<N_NODES / 64, 256>>>(Wh, adj, out);
}

extern "C" void kernel_launch(void* const* d_in, const int* in_sizes, int n_in,
                              void* d_out, int out_size) {
    const float* x      = (const float*)d_in[0];
    const int*   adj    = (const int*)d_in[1];
    const float* W1     = (const float*)d_in[2];
    const float* a1_src = (const float*)d_in[3];
    const float* a1_dst = (const float*)d_in[4];
    const float* W2     = (const float*)d_in[5];
    const float* a2_src = (const float*)d_in[6];
    const float* a2_dst = (const float*)d_in[7];
    float* out = (float*)d_out;

    float* h1;
    cudaGetSymbolAddress((void**)&h1, g_h1);

    run_layer(x, adj, W1, a1_src, a1_dst, h1);
    run_layer(h1, adj, W2, a2_src, a2_dst, out);
}

// round 3
// speedup vs baseline: 2.6443x; 1.4466x over previous
#include <cuda_runtime.h>
#include <cuda_bf16.h>
#include <cstdint>

// GAT 2-layer fused. Rank-1 logits: e[i,j] = lrelu(s_i + d_j), masked by adj.
// P generated on the fly inside a tf32 tensor-core P @ Wh GEMM.
// Stabilizer: m_i = lrelu(s_i + max_j d_j) (lrelu monotone).

#define N_NODES 8192
#define DIM 256

__device__ float g_Wh[N_NODES * DIM];    // fp32 Wh (for s/d)
__device__ float g_WhT[N_NODES * DIM];   // tf32-rounded Wh (V operand)
__device__ float g_h1[N_NODES * DIM];
__device__ float g_s[N_NODES];
__device__ float g_d[N_NODES];
__device__ float g_maxd;

__device__ __forceinline__ float lrelu(float x) { return x > 0.f ? x : 0.2f * x; }

__device__ __forceinline__ float tf32r(float x) {
    uint32_t u;
    asm("cvt.rna.tf32.f32 %0, %1;" : "=r"(u) : "f"(x));
    return __uint_as_float(u);
}

__device__ __forceinline__ void mma_tf32(float4& c, const uint32_t a[4],
                                         uint32_t b0, uint32_t b1) {
    asm volatile(
        "mma.sync.aligned.m16n8k8.row.col.f32.tf32.tf32.f32 "
        "{%0,%1,%2,%3}, {%4,%5,%6,%7}, {%8,%9}, {%0,%1,%2,%3};"
        : "+f"(c.x), "+f"(c.y), "+f"(c.z), "+f"(c.w)
        : "r"(a[0]), "r"(a[1]), "r"(a[2]), "r"(a[3]), "r"(b0), "r"(b1));
}

__device__ __forceinline__ void cp_async16(uint32_t smem_dst, const void* gsrc) {
    asm volatile("cp.async.cg.shared.global [%0], [%1], 16;" ::
                 "r"(smem_dst), "l"(gsrc));
}

// ---------------------------------------------------------------------------
// GEMM: C[N,D] = A[N,D] @ B[D,D]  (Wh = h @ W). Also emits tf32-rounded copy.
// ---------------------------------------------------------------------------
__global__ void __launch_bounds__(256) gemm_wh(const float* __restrict__ A,
                                               const float* __restrict__ B,
                                               float* __restrict__ C,
                                               float* __restrict__ CT) {
    __shared__ float As[64 * 16];
    __shared__ float Bs[16 * 64];
    const int t = threadIdx.x;
    const int tx = t & 15;
    const int ty = t >> 4;
    const int i0 = blockIdx.y * 64;
    const int c0 = blockIdx.x * 64;

    float acc[4][4] = {};

    for (int k0 = 0; k0 < DIM; k0 += 16) {
        __syncthreads();
        {
            int e = t * 4;
            int r = e >> 4, kk = e & 15;
            *(float4*)&As[e] = *(const float4*)&A[(size_t)(i0 + r) * DIM + k0 + kk];
        }
        {
            int e = t * 4;
            int kr = e >> 6, cc = e & 63;
            *(float4*)&Bs[e] = *(const float4*)&B[(size_t)(k0 + kr) * DIM + c0 + cc];
        }
        __syncthreads();

        #pragma unroll
        for (int k = 0; k < 16; k++) {
            float a[4];
            #pragma unroll
            for (int m = 0; m < 4; m++) a[m] = As[(ty * 4 + m) * 16 + k];
            float4 bb = *(float4*)&Bs[k * 64 + tx * 4];
            float b[4] = {bb.x, bb.y, bb.z, bb.w};
            #pragma unroll
            for (int m = 0; m < 4; m++)
                #pragma unroll
                for (int n = 0; n < 4; n++)
                    acc[m][n] = fmaf(a[m], b[n], acc[m][n]);
        }
    }

    #pragma unroll
    for (int m = 0; m < 4; m++)
        #pragma unroll
        for (int n = 0; n < 4; n++) {
            size_t idx = (size_t)(i0 + ty * 4 + m) * DIM + c0 + tx * 4 + n;
            C[idx] = acc[m][n];
            CT[idx] = tf32r(acc[m][n]);
        }
}

// ---------------------------------------------------------------------------
__global__ void __launch_bounds__(256) compute_sd(const float* __restrict__ Wh,
                                                  const float* __restrict__ a_src,
                                                  const float* __restrict__ a_dst) {
    int warp = (blockIdx.x * blockDim.x + threadIdx.x) >> 5;
    int lane = threadIdx.x & 31;
    if (warp >= N_NODES) return;
    const float* row = Wh + (size_t)warp * DIM;
    float ps = 0.f, pd = 0.f;
    #pragma unroll
    for (int c = lane; c < DIM; c += 32) {
        float v = row[c];
        ps = fmaf(v, a_src[c], ps);
        pd = fmaf(v, a_dst[c], pd);
    }
    #pragma unroll
    for (int o = 16; o > 0; o >>= 1) {
        ps += __shfl_down_sync(0xffffffffu, ps, o);
        pd += __shfl_down_sync(0xffffffffu, pd, o);
    }
    if (lane == 0) { g_s[warp] = ps; g_d[warp] = pd; }
}

__global__ void __launch_bounds__(1024) reduce_maxd() {
    __shared__ float sm[1024];
    int t = threadIdx.x;
    float m = -3.0e38f;
    for (int i = t; i < N_NODES; i += 1024) m = fmaxf(m, g_d[i]);
    sm[t] = m;
    __syncthreads();
    for (int o = 512; o > 0; o >>= 1) {
        if (t < o) sm[t] = fmaxf(sm[t], sm[t + o]);
        __syncthreads();
    }
    if (t == 0) g_maxd = sm[0];
}

// ---------------------------------------------------------------------------
// Fused attention * Wh on tf32 tensor cores.
// BM=32 rows, BN=256 (all cols), BK=32 over j. Double-buffered smem,
// V tiles via cp.async from pre-rounded g_WhT. 256 threads = 8 warps,
// warp grid 2(M) x 4(N); warp tile M16 x N64 -> 32 MMA/warp/iter.
// grid = N/32 = 256 blocks, 2 CTAs/SM.
// ---------------------------------------------------------------------------
#define PA_STRIDE 36    // 32 x 32 P tile rows (conflict-free A frags)
#define SV_STRIDE 264   // 32 x 256 V tile rows (conflict-free B frags)
#define PA_FLOATS (32 * PA_STRIDE)
#define SV_FLOATS (32 * SV_STRIDE)
#define SMEM_FLOATS (2 * PA_FLOATS + 2 * SV_FLOATS + 32)
#define SMEM_BYTES (SMEM_FLOATS * 4)

__global__ void __launch_bounds__(256, 2) gat_main(const float* __restrict__ WhT,
                                                   const int* __restrict__ adj,
                                                   float* __restrict__ out) {
    extern __shared__ float smem[];
    float* spA = smem;                       // [2][PA_FLOATS]
    float* sv = smem + 2 * PA_FLOATS;        // [2][SV_FLOATS]
    float* sz = sv + 2 * SV_FLOATS;          // [32]

    const int t = threadIdx.x;
    const int lane = t & 31;
    const int warp = t >> 5;
    const int warpM = warp >> 2;        // 0..1
    const int warpN = warp & 3;         // 0..3
    const int gid = lane >> 2;          // 0..7
    const int tig = lane & 3;           // 0..3
    const int i0 = blockIdx.x * 32;

    // P-generation: thread t covers row pr (0..31), cols kb..kb+3 (of 32)
    const int pr = t >> 3;
    const int kb = (t & 7) * 4;
    const float s_r = g_s[i0 + pr];
    const float m_r = lrelu(s_r + g_maxd);
    const int* adjrow = adj + (size_t)(i0 + pr) * N_NODES;

    float4 acc[8];
    #pragma unroll
    for (int n = 0; n < 8; n++) acc[n] = make_float4(0.f, 0.f, 0.f, 0.f);
    float zacc = 0.f;

    // V copy assignment: 2048 16B-chunks per tile, 8 per thread
    uint32_t sv_base[2];
    sv_base[0] = (uint32_t)__cvta_generic_to_shared(sv);
    sv_base[1] = (uint32_t)__cvta_generic_to_shared(sv + SV_FLOATS);

    // ---- prologue: fill buffer 0 ----
    {
        int4 aj = *(const int4*)&adjrow[kb];
        float4 dd = *(const float4*)&g_d[kb];
        float4 p;
        p.x = tf32r(aj.x ? __expf(lrelu(s_r + dd.x) - m_r) : 0.f);
        p.y = tf32r(aj.y ? __expf(lrelu(s_r + dd.y) - m_r) : 0.f);
        p.z = tf32r(aj.z ? __expf(lrelu(s_r + dd.z) - m_r) : 0.f);
        p.w = tf32r(aj.w ? __expf(lrelu(s_r + dd.w) - m_r) : 0.f);
        *(float4*)&spA[pr * PA_STRIDE + kb] = p;

        #pragma unroll
        for (int w = 0; w < 8; w++) {
            int idx = t + 256 * w;
            int row = idx >> 6, c4 = (idx & 63) * 4;
            cp_async16(sv_base[0] + (row * SV_STRIDE + c4) * 4,
                       WhT + (size_t)row * DIM + c4);
        }
        asm volatile("cp.async.commit_group;" ::: "memory");
    }

    const int NIT = N_NODES / 32;   // 256
    for (int it = 0; it < NIT; ++it) {
        const int cur = it & 1, nxt = cur ^ 1;
        const int jn = (it + 1 < NIT) ? (it + 1) * 32 : 0;

        // prefetch next adj/d into registers (overlaps everything below)
        int4 aj = *(const int4*)&adjrow[jn + kb];
        float4 dd = *(const float4*)&g_d[jn + kb];

        // wait for V[cur], make P[cur] visible, retire prior readers of nxt
        asm volatile("cp.async.wait_group 0;" ::: "memory");
        __syncthreads();

        // issue V[nxt] copies (complete during the MMA below)
        #pragma unroll
        for (int w = 0; w < 8; w++) {
            int idx = t + 256 * w;
            int row = idx >> 6, c4 = (idx & 63) * 4;
            cp_async16(sv_base[nxt] + (row * SV_STRIDE + c4) * 4,
                       WhT + (size_t)(jn + row) * DIM + c4);
        }
        asm volatile("cp.async.commit_group;" ::: "memory");

        const float* A = spA + cur * PA_FLOATS;
        const float* V = sv + cur * SV_FLOATS;

        // Z accumulation (threads 0..31, row t)
        if (t < 32) {
            float zz = 0.f;
            #pragma unroll
            for (int k = 0; k < 32; k++) zz += A[t * PA_STRIDE + k];
            zacc += zz;
        }

        // tensor-core GEMM on current tiles
        #pragma unroll
        for (int kc = 0; kc < 4; kc++) {
            const int c = kc * 8 + tig;
            uint32_t a[4];
            {
                const int r = warpM * 16 + gid;
                a[0] = __float_as_uint(A[r * PA_STRIDE + c]);
                a[1] = __float_as_uint(A[(r + 8) * PA_STRIDE + c]);
                a[2] = __float_as_uint(A[r * PA_STRIDE + c + 4]);
                a[3] = __float_as_uint(A[(r + 8) * PA_STRIDE + c + 4]);
            }
            #pragma unroll
            for (int nt = 0; nt < 8; nt++) {
                int n = warpN * 64 + nt * 8 + gid;
                uint32_t b0 = __float_as_uint(V[c * SV_STRIDE + n]);
                uint32_t b1 = __float_as_uint(V[(c + 4) * SV_STRIDE + n]);
                mma_tf32(acc[nt], a, b0, b1);
            }
        }

        // write P[nxt] (prev readers of nxt finished before this iter's sync)
        {
            float4 p;
            p.x = tf32r(aj.x ? __expf(lrelu(s_r + dd.x) - m_r) : 0.f);
            p.y = tf32r(aj.y ? __expf(lrelu(s_r + dd.y) - m_r) : 0.f);
            p.z = tf32r(aj.z ? __expf(lrelu(s_r + dd.z) - m_r) : 0.f);
            p.w = tf32r(aj.w ? __expf(lrelu(s_r + dd.w) - m_r) : 0.f);
            *(float4*)&spA[nxt * PA_FLOATS + pr * PA_STRIDE + kb] = p;
        }
    }

    if (t < 32) sz[t] = zacc;
    __syncthreads();

    // epilogue: divide by Z, relu, store
    {
        int rloc0 = warpM * 16 + gid;
        int rloc1 = rloc0 + 8;
        float z0 = sz[rloc0], z1 = sz[rloc1];
        float rz0 = (z0 > 0.f) ? (1.f / z0) : 0.f;
        float rz1 = (z1 > 0.f) ? (1.f / z1) : 0.f;
        #pragma unroll
        for (int nt = 0; nt < 8; nt++) {
            int col = warpN * 64 + nt * 8 + 2 * tig;
            float4 c = acc[nt];
            float2 o0 = make_float2(fmaxf(c.x * rz0, 0.f), fmaxf(c.y * rz0, 0.f));
            float2 o1 = make_float2(fmaxf(c.z * rz1, 0.f), fmaxf(c.w * rz1, 0.f));
            *(float2*)&out[(size_t)(i0 + rloc0) * DIM + col] = o0;
            *(float2*)&out[(size_t)(i0 + rloc1) * DIM + col] = o1;
        }
    }
}

// ---------------------------------------------------------------------------
static void run_layer(const float* h_in, const int* adj, const float* W,
                      const float* a_src, const float* a_dst, float* out) {
    float *Wh, *WhT;
    cudaGetSymbolAddress((void**)&Wh, g_Wh);
    cudaGetSymbolAddress((void**)&WhT, g_WhT);

    dim3 ggrid(DIM / 64, N_NODES / 64);
    gemm_wh<<<ggrid, 256>>>(h_in, W, Wh, WhT);
    compute_sd<<<(N_NODES * 32) / 256, 256>>>(Wh, a_src, a_dst);
    reduce_maxd<<<1, 1024>>>();
    gat_main<<<N_NODES / 32, 256, SMEM_BYTES>>>(WhT, adj, out);
}

extern "C" void kernel_launch(void* const* d_in, const int* in_sizes, int n_in,
                              void* d_out, int out_size) {
    const float* x      = (const float*)d_in[0];
    const int*   adj    = (const int*)d_in[1];
    const float* W1     = (const float*)d_in[2];
    const float* a1_src = (const float*)d_in[3];
    const float* a1_dst = (const float*)d_in[4];
    const float* W2     = (const float*)d_in[5];
    const float* a2_src = (const float*)d_in[6];
    const float* a2_dst = (const float*)d_in[7];
    float* out = (float*)d_out;

    cudaFuncSetAttribute(gat_main, cudaFuncAttributeMaxDynamicSharedMemorySize,
                         SMEM_BYTES);

    float* h1;
    cudaGetSymbolAddress((void**)&h1, g_h1);

    run_layer(x, adj, W1, a1_src, a1_dst, h1);
    run_layer(h1, adj, W2, a2_src, a2_dst, out);
}

// round 7
// speedup vs baseline: 4.0473x; 1.5306x over previous
#include <cuda_runtime.h>
#include <cstdint>

#define N_NODES 8192
#define DIM 256
#define SPLIT 2
#define KSPAN (N_NODES / SPLIT)   // 4096
#define BK 32
#define NCH (KSPAN / BK)          // 128 iters per CTA
#define BM 64
#define NCHUNK_TOT (N_NODES / BK) // 256 packed V chunks

// ---- device scratch (static only) ----
__device__ float  g_Wh[N_NODES * DIM];          // fp32 Wh
__device__ float2 g_Vp[NCHUNK_TOT * 16 * 256];  // packed tf32 V pairs (8 MB)
__device__ float  g_h1[N_NODES * DIM];
__device__ float  g_Dp[SPLIT][N_NODES * DIM];   // split-K partial numerators
__device__ float  g_Zp[SPLIT][N_NODES];         // split-K partial Z
__device__ float  g_s[N_NODES];
__device__ float  g_d[N_NODES];
__device__ float  g_maxd;

__device__ __forceinline__ float lrelu(float x) { return x > 0.f ? x : 0.2f * x; }

__device__ __forceinline__ float tf32r(float x) {
    uint32_t u;
    asm("cvt.rna.tf32.f32 %0, %1;" : "=r"(u) : "f"(x));
    return __uint_as_float(u);
}

__device__ __forceinline__ void mma_tf32(float4& c, const uint32_t a[4],
                                         uint32_t b0, uint32_t b1) {
    asm volatile(
        "mma.sync.aligned.m16n8k8.row.col.f32.tf32.tf32.f32 "
        "{%0,%1,%2,%3}, {%4,%5,%6,%7}, {%8,%9}, {%0,%1,%2,%3};"
        : "+f"(c.x), "+f"(c.y), "+f"(c.z), "+f"(c.w)
        : "r"(a[0]), "r"(a[1]), "r"(a[2]), "r"(a[3]), "r"(b0), "r"(b1));
}

__device__ __forceinline__ void cp_async16(uint32_t dst, const void* src) {
    asm volatile("cp.async.cg.shared.global [%0], [%1], 16;" :: "r"(dst), "l"(src));
}

// ---------------------------------------------------------------------------
// GEMM: Wh = h @ W (fp32 SIMT, ~1 GFLOP)
// ---------------------------------------------------------------------------
__global__ void __launch_bounds__(256) gemm_wh(const float* __restrict__ A,
                                               const float* __restrict__ B,
                                               float* __restrict__ C) {
    __shared__ float As[64 * 16];
    __shared__ float Bs[16 * 64];
    const int t = threadIdx.x;
    const int tx = t & 15;
    const int ty = t >> 4;
    const int i0 = blockIdx.y * 64;
    const int c0 = blockIdx.x * 64;

    float acc[4][4] = {};
    for (int k0 = 0; k0 < DIM; k0 += 16) {
        __syncthreads();
        {
            int e = t * 4;
            int r = e >> 4, kk = e & 15;
            *(float4*)&As[e] = *(const float4*)&A[(size_t)(i0 + r) * DIM + k0 + kk];
        }
        {
            int e = t * 4;
            int kr = e >> 6, cc = e & 63;
            *(float4*)&Bs[e] = *(const float4*)&B[(size_t)(k0 + kr) * DIM + c0 + cc];
        }
        __syncthreads();
        #pragma unroll
        for (int k = 0; k < 16; k++) {
            float a[4];
            #pragma unroll
            for (int m = 0; m < 4; m++) a[m] = As[(ty * 4 + m) * 16 + k];
            float4 bb = *(float4*)&Bs[k * 64 + tx * 4];
            float b[4] = {bb.x, bb.y, bb.z, bb.w};
            #pragma unroll
            for (int m = 0; m < 4; m++)
                #pragma unroll
                for (int n = 0; n < 4; n++)
                    acc[m][n] = fmaf(a[m], b[n], acc[m][n]);
        }
    }
    #pragma unroll
    for (int m = 0; m < 4; m++)
        #pragma unroll
        for (int n = 0; n < 4; n++)
            C[(size_t)(i0 + ty * 4 + m) * DIM + c0 + tx * 4 + n] = acc[m][n];
}

// ---------------------------------------------------------------------------
// Pack V: for chunk c, row rp, col n:
//   g_Vp[(c*16+rp)*256+n] = (tf32(Wh[j0][n]), tf32(Wh[j0+4][n]))
//   j0 = c*32 + (rp>>2)*8 + (rp&3)
// ---------------------------------------------------------------------------
__global__ void __launch_bounds__(256) vpack(const float* __restrict__ Wh,
                                             float2* __restrict__ Vp) {
    const int c = blockIdx.x;
    const int t = threadIdx.x;
    #pragma unroll
    for (int w = 0; w < 16; w++) {
        int j0 = c * 32 + (w >> 2) * 8 + (w & 3);
        float v0 = Wh[(size_t)j0 * DIM + t];
        float v1 = Wh[(size_t)(j0 + 4) * DIM + t];
        Vp[(size_t)(c * 16 + w) * 256 + t] = make_float2(tf32r(v0), tf32r(v1));
    }
}

// ---------------------------------------------------------------------------
__global__ void __launch_bounds__(256) compute_sd(const float* __restrict__ Wh,
                                                  const float* __restrict__ a_src,
                                                  const float* __restrict__ a_dst) {
    int warp = (blockIdx.x * blockDim.x + threadIdx.x) >> 5;
    int lane = threadIdx.x & 31;
    if (warp >= N_NODES) return;
    const float* row = Wh + (size_t)warp * DIM;
    float ps = 0.f, pd = 0.f;
    #pragma unroll
    for (int c = lane; c < DIM; c += 32) {
        float v = row[c];
        ps = fmaf(v, a_src[c], ps);
        pd = fmaf(v, a_dst[c], pd);
    }
    #pragma unroll
    for (int o = 16; o > 0; o >>= 1) {
        ps += __shfl_down_sync(0xffffffffu, ps, o);
        pd += __shfl_down_sync(0xffffffffu, pd, o);
    }
    if (lane == 0) { g_s[warp] = ps; g_d[warp] = pd; }
}

__global__ void __launch_bounds__(1024) reduce_maxd() {
    __shared__ float sm[1024];
    int t = threadIdx.x;
    float m = -3.0e38f;
    for (int i = t; i < N_NODES; i += 1024) m = fmaxf(m, g_d[i]);
    sm[t] = m;
    __syncthreads();
    for (int o = 512; o > 0; o >>= 1) {
        if (t < o) sm[t] = fmaxf(sm[t], sm[t + o]);
        __syncthreads();
    }
    if (t == 0) g_maxd = sm[0];
}

// ---------------------------------------------------------------------------
// Fused attention * Wh on tf32 mma.sync.
// BM=64, BN=256, BK=32, split-K=2. 256 threads = 8 warps (2M x 4N),
// warp tile M32 x N64 (2 m-tiles). B fragments are packed float2 pairs.
// grid (128, 2), 2 CTAs/SM.
// ---------------------------------------------------------------------------
#define PA_STRIDE 36
#define PA_FLOATS (64 * PA_STRIDE)          // 2304
#define VROW 520                            // 512 data + 8 pad (==8 mod 32)
#define VP_FLOATS (16 * VROW)               // 8320
#define SMEM_FLOATS (2 * PA_FLOATS + 2 * VP_FLOATS)
#define SMEM_BYTES (SMEM_FLOATS * 4 + 16)

__global__ void __launch_bounds__(256, 2) gat_mma(const float2* __restrict__ Vp,
                                                  const int* __restrict__ adj,
                                                  float* __restrict__ Dp,
                                                  float* __restrict__ Zp) {
    extern __shared__ float smem[];
    float* spA = smem;                      // [2][PA_FLOATS]
    float* svp = smem + 2 * PA_FLOATS;      // [2][VP_FLOATS]

    const int t = threadIdx.x;
    const int lane = t & 31;
    const int warp = t >> 5;
    const int warpM = warp >> 2;            // 0..1
    const int warpN = warp & 3;             // 0..3
    const int gid = lane >> 2;              // 0..7
    const int tig = lane & 3;               // 0..3
    const int i0 = blockIdx.x * BM;
    const int split = blockIdx.y;
    const int ch0 = split * (NCHUNK_TOT / SPLIT);   // first packed chunk

    Dp += (size_t)split * N_NODES * DIM;
    Zp += (size_t)split * N_NODES;

    // P producer: thread -> row pr (0..63), cols kb..kb+7 (of 32)
    const int pr = t >> 2;
    const int kb = (t & 3) * 8;
    const float s_r = g_s[i0 + pr];
    const float m_r = lrelu(s_r + g_maxd);
    const int* adjrow = adj + (size_t)(i0 + pr) * N_NODES + split * KSPAN;
    const float* dbase = g_d + split * KSPAN;

    float4 acc[2][8];
    #pragma unroll
    for (int m = 0; m < 2; m++)
        #pragma unroll
        for (int n = 0; n < 8; n++) acc[m][n] = make_float4(0.f, 0.f, 0.f, 0.f);
    float zacc = 0.f;

    const uint32_t sv_u32 = (uint32_t)__cvta_generic_to_shared(svp);

    // helper lambdas (inlined)
    auto produce_P = [&](float* buf, const int4 aj[2], const float4 dv[2]) {
        float p[8];
        p[0] = aj[0].x ? __expf(lrelu(s_r + dv[0].x) - m_r) : 0.f;
        p[1] = aj[0].y ? __expf(lrelu(s_r + dv[0].y) - m_r) : 0.f;
        p[2] = aj[0].z ? __expf(lrelu(s_r + dv[0].z) - m_r) : 0.f;
        p[3] = aj[0].w ? __expf(lrelu(s_r + dv[0].w) - m_r) : 0.f;
        p[4] = aj[1].x ? __expf(lrelu(s_r + dv[1].x) - m_r) : 0.f;
        p[5] = aj[1].y ? __expf(lrelu(s_r + dv[1].y) - m_r) : 0.f;
        p[6] = aj[1].z ? __expf(lrelu(s_r + dv[1].z) - m_r) : 0.f;
        p[7] = aj[1].w ? __expf(lrelu(s_r + dv[1].w) - m_r) : 0.f;
        zacc += ((p[0] + p[1]) + (p[2] + p[3])) + ((p[4] + p[5]) + (p[6] + p[7]));
        float* dst = buf + pr * PA_STRIDE + kb;
        *(float4*)dst = make_float4(tf32r(p[0]), tf32r(p[1]), tf32r(p[2]), tf32r(p[3]));
        *(float4*)(dst + 4) = make_float4(tf32r(p[4]), tf32r(p[5]), tf32r(p[6]), tf32r(p[7]));
    };

    auto issue_V = [&](int buf, int chunk) {
        const char* gsrc = (const char*)(Vp + (size_t)chunk * 16 * 256);
        uint32_t base = sv_u32 + buf * (VP_FLOATS * 4);
        #pragma unroll
        for (int w = 0; w < 8; w++) {
            int qid = t + 256 * w;           // 16B chunk id (0..2047)
            int rp = qid >> 7;
            int off = (qid & 127) * 16;
            cp_async16(base + rp * (VROW * 4) + off, gsrc + qid * 16);
        }
        asm volatile("cp.async.commit_group;" ::: "memory");
    };

    // ---- prologue: chunk 0 into buffer 0 ----
    {
        int4 aj[2]; float4 dv[2];
        aj[0] = *(const int4*)&adjrow[kb];
        aj[1] = *(const int4*)&adjrow[kb + 4];
        dv[0] = *(const float4*)&dbase[kb];
        dv[1] = *(const float4*)&dbase[kb + 4];
        produce_P(spA, aj, dv);
        issue_V(0, ch0);
    }

    for (int it = 0; it < NCH; ++it) {
        const int cur = it & 1, nxt = cur ^ 1;

        int4 aj[2]; float4 dv[2];
        const bool more = (it + 1 < NCH);
        if (more) {
            const int jc = (it + 1) * BK;
            aj[0] = *(const int4*)&adjrow[jc + kb];
            aj[1] = *(const int4*)&adjrow[jc + kb + 4];
            dv[0] = *(const float4*)&dbase[jc + kb];
            dv[1] = *(const float4*)&dbase[jc + kb + 4];
        }

        asm volatile("cp.async.wait_group 0;" ::: "memory");
        __syncthreads();   // P[cur] + V[cur] visible; nxt free

        if (more) issue_V(nxt, ch0 + it + 1);

        const float* A = spA + cur * PA_FLOATS;
        const float* Vb = svp + cur * VP_FLOATS;

        #pragma unroll
        for (int kc = 0; kc < 4; kc++) {
            uint32_t a[2][4];
            #pragma unroll
            for (int mt = 0; mt < 2; mt++) {
                const int r = warpM * 32 + mt * 16 + gid;
                const int c = kc * 8 + tig;
                a[mt][0] = __float_as_uint(A[r * PA_STRIDE + c]);
                a[mt][1] = __float_as_uint(A[(r + 8) * PA_STRIDE + c]);
                a[mt][2] = __float_as_uint(A[r * PA_STRIDE + c + 4]);
                a[mt][3] = __float_as_uint(A[(r + 8) * PA_STRIDE + c + 4]);
            }
            const float* vrow = Vb + (kc * 4 + tig) * VROW;
            #pragma unroll
            for (int nt = 0; nt < 8; nt++) {
                const int n = warpN * 64 + nt * 8 + gid;
                float2 b = *(const float2*)&vrow[n * 2];
                uint32_t b0 = __float_as_uint(b.x);
                uint32_t b1 = __float_as_uint(b.y);
                mma_tf32(acc[0][nt], a[0], b0, b1);
                mma_tf32(acc[1][nt], a[1], b0, b1);
            }
        }

        if (more) produce_P(spA + nxt * PA_FLOATS, aj, dv);
    }

    // ---- Z partials (4 producer threads per row -> shfl reduce) ----
    {
        float z = zacc;
        z += __shfl_xor_sync(0xffffffffu, z, 1);
        z += __shfl_xor_sync(0xffffffffu, z, 2);
        if ((t & 3) == 0) Zp[i0 + pr] = z;
    }

    // ---- store partial numerators ----
    #pragma unroll
    for (int mt = 0; mt < 2; mt++) {
        const int r0 = warpM * 32 + mt * 16 + gid;
        const int r1 = r0 + 8;
        #pragma unroll
        for (int nt = 0; nt < 8; nt++) {
            const int col = warpN * 64 + nt * 8 + 2 * tig;
            float4 c = acc[mt][nt];
            *(float2*)&Dp[(size_t)(i0 + r0) * DIM + col] = make_float2(c.x, c.y);
            *(float2*)&Dp[(size_t)(i0 + r1) * DIM + col] = make_float2(c.z, c.w);
        }
    }
}

// ---------------------------------------------------------------------------
// out[i,n] = relu((D0+D1)[i,n] / (Z0+Z1)[i])
// ---------------------------------------------------------------------------
__global__ void __launch_bounds__(256) combine_out(float* __restrict__ out) {
    int idx = blockIdx.x * 256 + threadIdx.x;     // float4 index
    int row = idx >> 6;
    float4 a = ((const float4*)g_Dp[0])[idx];
    float4 b = ((const float4*)g_Dp[1])[idx];
    float z = g_Zp[0][row] + g_Zp[1][row];
    float rz = (z > 0.f) ? 1.f / z : 0.f;
    float4 o;
    o.x = fmaxf((a.x + b.x) * rz, 0.f);
    o.y = fmaxf((a.y + b.y) * rz, 0.f);
    o.z = fmaxf((a.z + b.z) * rz, 0.f);
    o.w = fmaxf((a.w + b.w) * rz, 0.f);
    ((float4*)out)[idx] = o;
}

// ---------------------------------------------------------------------------
static void run_layer(const float* h_in, const int* adj, const float* W,
                      const float* a_src, const float* a_dst, float* out) {
    float *Wh, *Dp, *Zp;
    float2* Vp;
    cudaGetSymbolAddress((void**)&Wh, g_Wh);
    cudaGetSymbolAddress((void**)&Vp, g_Vp);
    cudaGetSymbolAddress((void**)&Dp, g_Dp);
    cudaGetSymbolAddress((void**)&Zp, g_Zp);

    gemm_wh<<<dim3(DIM / 64, N_NODES / 64), 256>>>(h_in, W, Wh);
    vpack<<<NCHUNK_TOT, 256>>>(Wh, Vp);
    compute_sd<<<(N_NODES * 32) / 256, 256>>>(Wh, a_src, a_dst);
    reduce_maxd<<<1, 1024>>>();
    gat_mma<<<dim3(N_NODES / BM, SPLIT), 256, SMEM_BYTES>>>(Vp, adj, Dp, Zp);
    combine_out<<<(N_NODES * DIM / 4) / 256, 256>>>(out);
}

extern "C" void kernel_launch(void* const* d_in, const int* in_sizes, int n_in,
                              void* d_out, int out_size) {
    const float* x      = (const float*)d_in[0];
    const int*   adj    = (const int*)d_in[1];
    const float* W1     = (const float*)d_in[2];
    const float* a1_src = (const float*)d_in[3];
    const float* a1_dst = (const float*)d_in[4];
    const float* W2     = (const float*)d_in[5];
    const float* a2_src = (const float*)d_in[6];
    const float* a2_dst = (const float*)d_in[7];
    float* out = (float*)d_out;

    cudaFuncSetAttribute(gat_mma, cudaFuncAttributeMaxDynamicSharedMemorySize,
                         SMEM_BYTES);

    float* h1;
    cudaGetSymbolAddress((void**)&h1, g_h1);

    run_layer(x, adj, W1, a1_src, a1_dst, h1);
    run_layer(h1, adj, W2, a2_src, a2_dst, out);
}